// round 14
// baseline (speedup 1.0000x reference)
#include <cuda_runtime.h>
#include <cuda_bf16.h>

// USER_NUM=1000, SKILL_NUM=256, K_HIDDEN=128, N_ITEMS=4096, SEQ_LEN=8192
// out[l, k] = sum_{s : Q[items[l], s] != 0} E[user, s, k]
//
// SINGLE persistent kernel, perfectly balanced (R13 lesson: grid-stride
// rounding doubled the wall time of both phases):
//   grid = 1024 CTAs x 256 thr = 8192 warps  -> exactly 1 phase-A task/warp
//                               = 262144 thr -> exactly 1 float4/thread in B
//   launch_bounds(256,7) => <=36 regs => 7 CTAs/SM => 1036 slots >= 1024:
//   all CTAs co-resident -> spin barrier is deadlock-free.

#define SEQ_LEN   8192
#define N_ITEMS   4096
#define SKILLS    256
#define K_HIDDEN  128
#define NNZ_CAP   64          // binomial(128,0.1): mean 12.8, std 3.4
#define GRID_CTAS 1024
#define CTA_THREADS 256
#define CTA_WARPS  (CTA_THREADS / 32)

// Partial sums: 8192 x 32 float4 = 4 MB static device scratch (no alloc)
__device__ float4   g_partial[2 * N_ITEMS * (K_HIDDEN / 4)];
// Monotonic barrier counter: zero-initialized at module load; never reset.
__device__ unsigned g_arrive;

__global__ void __launch_bounds__(CTA_THREADS, 7)
fused_balanced(const int* __restrict__ user_p,
               const float* __restrict__ Q,     // [N_ITEMS, SKILLS]
               const int* __restrict__ items,   // [SEQ_LEN]
               const float* __restrict__ emb,   // [USER_NUM, SKILLS, K_HIDDEN]
               float4* __restrict__ out4)       // [SEQ_LEN * 32]
{
    __shared__ int      sidx[CTA_WARPS][NNZ_CAP];
    __shared__ unsigned s_target;

    const int tid  = threadIdx.x;
    const int w    = tid >> 5;
    const int lane = tid & 31;

    // ================= Phase A: one item-half task per warp ================
    {
        const int task = blockIdx.x * CTA_WARPS + w;   // 0 .. 8191, exact
        const int item = task >> 1;
        const int half = task & 1;

        const int user = user_p[0];
        const float4* __restrict__ E4 =
            reinterpret_cast<const float4*>(emb + (long long)user * SKILLS * K_HIDDEN) + lane;

        // This half's 128 skills: one coalesced float4 per lane
        const float4 v = reinterpret_cast<const float4*>(
            Q + (long long)item * SKILLS + half * 128)[lane];

        // Ballot-compact nonzero skill ids into smem
        const int s_base = half * 128 + 4 * lane;
        const float vals[4] = {v.x, v.y, v.z, v.w};
        const unsigned lt_mask = (1u << lane) - 1u;
        int nnz = 0;
        #pragma unroll
        for (int t = 0; t < 4; t++) {
            const bool nz = (vals[t] != 0.0f);
            const unsigned m = __ballot_sync(0xffffffffu, nz);
            if (nz) {
                const int p = nnz + __popc(m & lt_mask);
                if (p < NNZ_CAP) sidx[w][p] = s_base + t;
            }
            nnz += __popc(m);
        }
        __syncwarp();
        nnz = min(nnz, NNZ_CAP);

        // Gather-accumulate: batches of 4 independent LDG.128 (reg-lean)
        float4 acc = make_float4(0.f, 0.f, 0.f, 0.f);
        int j = 0;
        for (; j + 4 <= nnz; j += 4) {
            const int s0 = sidx[w][j+0], s1 = sidx[w][j+1];
            const int s2 = sidx[w][j+2], s3 = sidx[w][j+3];
            const float4 e0 = E4[s0 * 32];
            const float4 e1 = E4[s1 * 32];
            const float4 e2 = E4[s2 * 32];
            const float4 e3 = E4[s3 * 32];
            acc.x += (e0.x + e1.x) + (e2.x + e3.x);
            acc.y += (e0.y + e1.y) + (e2.y + e3.y);
            acc.z += (e0.z + e1.z) + (e2.z + e3.z);
            acc.w += (e0.w + e1.w) + (e2.w + e3.w);
        }
        for (; j < nnz; j++) {
            const float4 e = E4[sidx[w][j] * 32];
            acc.x += e.x; acc.y += e.y; acc.z += e.z; acc.w += e.w;
        }

        g_partial[task * 32 + lane] = acc;   // halves of an item adjacent
    }

    // ================= Device-wide barrier (replay-safe, no reset) =========
    __syncthreads();
    if (tid == 0) {
        __threadfence();                                  // release phase-A writes
        const unsigned ticket = atomicAdd(&g_arrive, 1u);
        // This replay's batch ends at (ticket - ticket%G) + G
        s_target = ticket - (ticket % GRID_CTAS) + GRID_CTAS;
    }
    __syncthreads();
    if (tid == 0) {
        const unsigned target = s_target;
        unsigned v;
        do {
            asm volatile("ld.acquire.gpu.u32 %0, [%1];"
                         : "=r"(v) : "l"(&g_arrive) : "memory");
        } while ((int)(v - target) < 0);                  // wrap-safe compare
    }
    __syncthreads();                                      // CTA-level ordering

    // ================= Phase B: out[g] = P[2*it] + P[2*it+1], exact ========
    {
        const int g   = blockIdx.x * CTA_THREADS + tid;   // 0 .. 262143, exact
        const int pos = g >> 5;
        const int q   = g & 31;
        const int it  = __ldg(&items[pos]);
        const float4 r0 = g_partial[(it * 2)     * 32 + q];
        const float4 r1 = g_partial[(it * 2 + 1) * 32 + q];
        float4 o;
        o.x = r0.x + r1.x; o.y = r0.y + r1.y;
        o.z = r0.z + r1.z; o.w = r0.w + r1.w;
        out4[g] = o;
    }
}

extern "C" void kernel_launch(void* const* d_in, const int* in_sizes, int n_in,
                              void* d_out, int out_size)
{
    const int*   user  = nullptr;
    const float* Q     = nullptr;
    const int*   items = nullptr;
    const float* emb   = nullptr;

    for (int i = 0; i < n_in; i++) {
        switch (in_sizes[i]) {
            case 1:                        user  = (const int*)  d_in[i]; break;
            case N_ITEMS * SKILLS:         Q     = (const float*)d_in[i]; break;
            case SEQ_LEN:                  items = (const int*)  d_in[i]; break;
            case 1000 * SKILLS * K_HIDDEN: emb   = (const float*)d_in[i]; break;
            default: break;
        }
    }
    if (!user)  user  = (const int*)  d_in[0];
    if (!Q)     Q     = (const float*)d_in[1];
    if (!items) items = (const int*)  d_in[2];
    if (!emb)   emb   = (const float*)d_in[3];

    // ONE launch; 1024 CTAs, 7 CTAs/SM achievable -> all co-resident
    fused_balanced<<<GRID_CTAS, CTA_THREADS>>>(user, Q, items, emb, (float4*)d_out);
}